// round 15
// baseline (speedup 1.0000x reference)
#include <cuda_runtime.h>
#include <cuda_fp16.h>
#include <cstdint>

#define N_NODES 50000
#define N_EDGES 800000
#define DIN 128
#define DHID 128
#define NH 8
#define DK 16
#define TN 8
#define TE 8
#define NB 4
#define NCHUNK ((N_NODES + 1023) / 1024)

// ---------------- scratch (static device memory; no allocations) ----------------
__device__ __half g_W_h[4 * TN * DIN * DHID];          // fp16 Wk,Wq,Wv,Wa for tensor cores
__device__ __half g_lw_hi[DIN * DHID];                 // loopw fp16 high part
__device__ __half g_lw_lo[DIN * DHID];                 // loopw fp16 residual
__device__ __half g_kqv_h[3 * NH * N_NODES * DK];      // k,q,v fp16 [mat][h][n][16] (38.4 MB)
__device__ __half g_qt_h[(size_t)NH * N_NODES * TE * DK]; // (att@q)*pri*scale fp16 [h][n][et][16]
__device__ __half g_elog[(size_t)NH * N_EDGES];        // exp(logit) fp16 [h][p] (12.8MB, L2-resident)
__device__ __half g_agg_h[N_NODES * DHID];             // aggregated messages fp16 [n][128]
__device__ int    g_deg[N_NODES];
__device__ int    g_rowstart[N_NODES + 1];
__device__ int    g_cursor[N_NODES];
__device__ int    g_eidx[N_EDGES];                     // (et<<16)|src, sorted by dst
__device__ int    g_dst_s[N_EDGES];                    // dst, sorted (CSR order)
__device__ int    g_node_order[N_NODES];
__device__ int    g_ncount[TN];
__device__ int    g_tstart[TN + 1];
__device__ int    g_tcur[TN];
__device__ int    g_part[NCHUNK];
__device__ int    g_chunkoff[NCHUNK];

// ---------------- warp-mma helpers ----------------
__device__ __forceinline__ void ldsm_x4(unsigned& r0, unsigned& r1, unsigned& r2, unsigned& r3, unsigned addr) {
    asm volatile("ldmatrix.sync.aligned.m8n8.x4.shared.b16 {%0,%1,%2,%3}, [%4];"
                 : "=r"(r0), "=r"(r1), "=r"(r2), "=r"(r3) : "r"(addr));
}
__device__ __forceinline__ void ldsm_x4_t(unsigned& r0, unsigned& r1, unsigned& r2, unsigned& r3, unsigned addr) {
    asm volatile("ldmatrix.sync.aligned.m8n8.x4.trans.shared.b16 {%0,%1,%2,%3}, [%4];"
                 : "=r"(r0), "=r"(r1), "=r"(r2), "=r"(r3) : "r"(addr));
}
__device__ __forceinline__ void mma16816(float* c, unsigned a0, unsigned a1, unsigned a2, unsigned a3,
                                         unsigned b0, unsigned b1) {
    asm volatile("mma.sync.aligned.m16n8k16.row.col.f32.f16.f16.f32 "
                 "{%0,%1,%2,%3},{%4,%5,%6,%7},{%8,%9},{%0,%1,%2,%3};"
                 : "+f"(c[0]), "+f"(c[1]), "+f"(c[2]), "+f"(c[3])
                 : "r"(a0), "r"(a1), "r"(a2), "r"(a3), "r"(b0), "r"(b1));
}

// ---------------- init: zero counters ----------------
__global__ void k_init() {
    int i = blockIdx.x * blockDim.x + threadIdx.x;
    if (i < N_NODES) g_deg[i] = 0;
    if (i < TN) g_ncount[i] = 0;
}

// ---------------- build per-type weight matrices W[t] = comp[t] @ basis (fp16) ----------------
__global__ void k_prepW(const float* __restrict__ ck, const float* __restrict__ bk,
                        const float* __restrict__ cq, const float* __restrict__ bq,
                        const float* __restrict__ cv, const float* __restrict__ bv,
                        const float* __restrict__ ca, const float* __restrict__ ba) {
    int idx = blockIdx.x * blockDim.x + threadIdx.x;           // 4 * 8 * 16384
    if (idx >= 4 * TN * DIN * DHID) return;
    int m  = idx >> 17;           // matrix id
    int r  = idx & 131071;
    int t  = r >> 14;             // type
    int io = r & 16383;
    const float* comp;
    const float* basis;
    if (m == 0)      { comp = ck; basis = bk; }
    else if (m == 1) { comp = cq; basis = bq; }
    else if (m == 2) { comp = cv; basis = bv; }
    else             { comp = ca; basis = ba; }
    float acc = 0.f;
#pragma unroll
    for (int b = 0; b < NB; b++)
        acc += comp[t * NB + b] * basis[b * (DIN * DHID) + io];
    g_W_h[idx] = __float2half(acc);
}

// ---------------- loopw split into fp16 hi + lo ----------------
__global__ void k_prepL(const float* __restrict__ loopw) {
    int i = blockIdx.x * blockDim.x + threadIdx.x;
    if (i >= DIN * DHID) return;
    float w = loopw[i];
    __half hi = __float2half(w);
    g_lw_hi[i] = hi;
    g_lw_lo[i] = __float2half(w - __half2float(hi));
}

// ---------------- counts: node types + in-degrees ----------------
__global__ void k_count(const int* __restrict__ ntype, const int* __restrict__ dst) {
    int i = blockIdx.x * blockDim.x + threadIdx.x;
    if (i < N_NODES) atomicAdd(&g_ncount[ntype[i]], 1);
    if (i < N_EDGES) atomicAdd(&g_deg[dst[i]], 1);
}

// ---------------- parallel scan phase A ----------------
__global__ void k_scanA() {
    __shared__ int wsum[32];
    int tid = threadIdx.x;
    int chunk = blockIdx.x;
    int i = chunk * 1024 + tid;
    int v = (i < N_NODES) ? g_deg[i] : 0;
    int lane = tid & 31, w = tid >> 5;
    int s = v;
#pragma unroll
    for (int o = 1; o < 32; o <<= 1) {
        int t = __shfl_up_sync(0xffffffffu, s, o);
        if (lane >= o) s += t;
    }
    if (lane == 31) wsum[w] = s;
    __syncthreads();
    if (w == 0) {
        int x = wsum[lane];
#pragma unroll
        for (int o = 1; o < 32; o <<= 1) {
            int t = __shfl_up_sync(0xffffffffu, x, o);
            if (lane >= o) x += t;
        }
        wsum[lane] = x;
    }
    __syncthreads();
    int excl = s - v + (w > 0 ? wsum[w - 1] : 0);
    if (i < N_NODES) g_rowstart[i] = excl;
    if (tid == 1023) g_part[chunk] = excl + v;
}

// ---------------- scan phase B ----------------
__global__ void k_scanB() {
    if (threadIdx.x == 0) {
        int acc = 0;
        for (int c = 0; c < NCHUNK; c++) { g_chunkoff[c] = acc; acc += g_part[c]; }
        g_rowstart[N_NODES] = N_EDGES;
        int a2 = 0;
        g_tstart[0] = 0;
        for (int t = 0; t < TN; t++) { a2 += g_ncount[t]; g_tstart[t + 1] = a2; }
        for (int t = 0; t < TN; t++) g_tcur[t] = g_tstart[t];
    }
}

// ---------------- scan phase C ----------------
__global__ void k_scanC() {
    int i = blockIdx.x * 1024 + threadIdx.x;
    if (i < N_NODES) {
        int r = g_rowstart[i] + g_chunkoff[blockIdx.x];
        g_rowstart[i] = r;
        g_cursor[i] = r;
    }
}

// ---------------- scatter ----------------
__global__ void k_scatter(const int* __restrict__ ntype, const int* __restrict__ src,
                          const int* __restrict__ dst, const int* __restrict__ etype) {
    int i = blockIdx.x * blockDim.x + threadIdx.x;
    if (i < N_NODES) {
        int t = ntype[i];
        int p = atomicAdd(&g_tcur[t], 1);
        g_node_order[p] = i;
    }
    if (i < N_EDGES) {
        int d = dst[i];
        int p = atomicAdd(&g_cursor[d], 1);
        g_eidx[p] = (etype[i] << 16) | src[i];    // N_NODES < 65536
        g_dst_s[p] = d;
    }
}

// ---------------- projection GEMM via tensor cores (fp16 in, fp32 accum, fp16 out) ----------------
// tile: 64 nodes x 128 out, K=128 in 2 chunks of 64. 8 warps = 4M x 2N.
__global__ void k_proj(const float* __restrict__ x) {
    int t = blockIdx.y;
    int cnt = g_tstart[t + 1] - g_tstart[t];
    int tile = blockIdx.x * 64;
    if (tile >= cnt) return;

    __shared__ __align__(16) __half As[64][136];
    __shared__ __align__(16) __half Ws[64][136];
    __shared__ int rows[64];

    int tid = threadIdx.x;
    if (tid < 64) {
        int r = tile + tid;
        rows[tid] = (r < cnt) ? g_node_order[g_tstart[t] + r] : -1;
    }
    __syncthreads();

    // gathered x rows -> fp16 smem
    for (int i = tid; i < 64 * 32; i += 256) {
        int nr = i >> 5;
        int c4 = i & 31;
        float4 v = make_float4(0.f, 0.f, 0.f, 0.f);
        int g = rows[nr];
        if (g >= 0) v = ((const float4*)x)[g * 32 + c4];
        *((__half2*)&As[nr][c4 * 4])     = __floats2half2_rn(v.x, v.y);
        *((__half2*)&As[nr][c4 * 4 + 2]) = __floats2half2_rn(v.z, v.w);
    }

    int w = tid >> 5;
    int lane = tid & 31;
    int mr = (w & 3) * 16;            // M offset of this warp
    int nc = (w >> 2) * 64;           // N offset of this warp
    int lrow = (lane & 7) + ((lane >> 3) & 1) * 8;   // ldmatrix source row (within 16)
    int lcol8 = (lane >> 4) * 8;                     // ldmatrix 8-col group

    int r0 = mr + (lane >> 2);        // accumulator row (mma layout)
    int cb = nc + (lane & 3) * 2;     // accumulator col base

    for (int mat = 0; mat < 3; mat++) {
        float acc[8][4];
#pragma unroll
        for (int nt = 0; nt < 8; nt++) {
#pragma unroll
            for (int c = 0; c < 4; c++) acc[nt][c] = 0.f;
        }

        const __half* W = g_W_h + (mat * TN + t) * (DIN * DHID);
        for (int kc = 0; kc < 2; kc++) {
            __syncthreads();   // protects Ws rewrite (and As on first pass)
            for (int i = tid; i < 64 * 16; i += 256) {
                int r = i >> 4;
                int c8 = i & 15;
                *((uint4*)&Ws[r][c8 * 8]) = ((const uint4*)(W + (kc * 64 + r) * DHID))[c8];
            }
            __syncthreads();
#pragma unroll
            for (int ks = 0; ks < 4; ks++) {
                unsigned a0, a1, a2, a3;
                unsigned aAddr = (unsigned)__cvta_generic_to_shared(
                    &As[mr + lrow][kc * 64 + ks * 16 + lcol8]);
                ldsm_x4(a0, a1, a2, a3, aAddr);
#pragma unroll
                for (int np = 0; np < 4; np++) {
                    unsigned b0, b1, b2, b3;
                    unsigned bAddr = (unsigned)__cvta_generic_to_shared(
                        &Ws[ks * 16 + lrow][nc + np * 16 + lcol8]);
                    ldsm_x4_t(b0, b1, b2, b3, bAddr);
                    mma16816(acc[np * 2],     a0, a1, a2, a3, b0, b1);
                    mma16816(acc[np * 2 + 1], a0, a1, a2, a3, b2, b3);
                }
            }
        }
        // store fp16 to [mat][h][n][16]
        int g0 = rows[r0];
        int g1 = rows[r0 + 8];
#pragma unroll
        for (int nt = 0; nt < 8; nt++) {
            int c = cb + nt * 8;
            int h = c >> 4;
            int j = c & 15;
            size_t base = (size_t)(mat * NH + h) * N_NODES;
            if (g0 >= 0) {
                *((__half2*)&g_kqv_h[(base + g0) * DK + j]) = __floats2half2_rn(acc[nt][0], acc[nt][1]);
            }
            if (g1 >= 0) {
                *((__half2*)&g_kqv_h[(base + g1) * DK + j]) = __floats2half2_rn(acc[nt][2], acc[nt][3]);
            }
        }
    }
}

// ---------------- qt via tensor cores: qt = q @ B_att, [h][n][et][16] ----------------
__global__ void k_qt(const float* __restrict__ att, const float* __restrict__ pri) {
    int h = blockIdx.y;
    int tile = blockIdx.x * 64;
    int tid = threadIdx.x;

    __shared__ __align__(16) __half As[64][24];    // 64x16 A tile
    __shared__ __align__(16) __half Bs[16][136];   // 16x128 B tile

    int w = tid >> 5;
    int lane = tid & 31;
    int mr = (w & 3) * 16;
    int nc = (w >> 2) * 64;
    int lrow = (lane & 7) + ((lane >> 3) & 1) * 8;
    int lcol8 = (lane >> 4) * 8;
    int r0 = mr + (lane >> 2);
    int cb = nc + (lane & 3) * 2;

    // A tile: q rows (node-contiguous fp16)
    {
        const __half* src = g_kqv_h + (size_t)(1 * NH + h) * N_NODES * DK;
        if (tid < 128) {
            int r = tid >> 1;
            int hc = tid & 1;
            int node = tile + r;
            uint4 v = make_uint4(0u, 0u, 0u, 0u);
            if (node < N_NODES) v = *((const uint4*)(src + (size_t)node * DK + hc * 8));
            *((uint4*)&As[r][hc * 8]) = v;
        }
    }
    // B tile: att * pri * scale
    for (int e = tid; e < 16 * 128; e += 256) {
        int i = e >> 7;
        int c = e & 127;
        int et = c >> 4;
        int j = c & 15;
        Bs[i][c] = __float2half(att[(et * NH + h) * 256 + i * 16 + j] * pri[et * NH + h] * 0.25f);
    }
    __syncthreads();

    float acc[8][4];
#pragma unroll
    for (int nt = 0; nt < 8; nt++) {
#pragma unroll
        for (int c = 0; c < 4; c++) acc[nt][c] = 0.f;
    }
    unsigned a0, a1, a2, a3;
    unsigned aAddr = (unsigned)__cvta_generic_to_shared(&As[mr + lrow][lcol8]);
    ldsm_x4(a0, a1, a2, a3, aAddr);
#pragma unroll
    for (int np = 0; np < 4; np++) {
        unsigned b0, b1, b2, b3;
        unsigned bAddr = (unsigned)__cvta_generic_to_shared(&Bs[lrow][nc + np * 16 + lcol8]);
        ldsm_x4_t(b0, b1, b2, b3, bAddr);
        mma16816(acc[np * 2],     a0, a1, a2, a3, b0, b1);
        mma16816(acc[np * 2 + 1], a0, a1, a2, a3, b2, b3);
    }

    int n0 = tile + r0;
    int n1 = tile + r0 + 8;
#pragma unroll
    for (int nt = 0; nt < 8; nt++) {
        int c = cb + nt * 8;
        if (n0 < N_NODES) {
            *((__half2*)&g_qt_h[((size_t)h * N_NODES + n0) * 128 + c]) =
                __floats2half2_rn(acc[nt][0], acc[nt][1]);
        }
        if (n1 < N_NODES) {
            *((__half2*)&g_qt_h[((size_t)h * N_NODES + n1) * 128 + c]) =
                __floats2half2_rn(acc[nt][2], acc[nt][3]);
        }
    }
}

// ---------------- edge attention: exp(logit) directly (|logit| << 1, max-shift unnecessary) ----------------
__global__ void k_logits() {
    int p = blockIdx.x * blockDim.x + threadIdx.x;
    int h = blockIdx.y;
    if (p >= N_EDGES) return;
    int e = g_eidx[p];
    int et = e >> 16;
    int s = e & 0xFFFF;
    int d = g_dst_s[p];
    const uint4* kk4 = (const uint4*)(g_kqv_h + ((size_t)h * N_NODES + s) * DK);
    const uint4* qt4 = (const uint4*)(g_qt_h + ((size_t)h * N_NODES + d) * 128 + et * DK);
    uint4 ka = kk4[0], kb = kk4[1];
    uint4 qa = qt4[0], qb = qt4[1];
    const __half2* kh = (const __half2*)&ka;
    const __half2* qh = (const __half2*)&qa;
    float acc = 0.f;
#pragma unroll
    for (int c = 0; c < 4; c++) {
        float2 a = __half22float2(kh[c]);
        float2 b = __half22float2(qh[c]);
        acc += a.x * b.x + a.y * b.y;
    }
    kh = (const __half2*)&kb;
    qh = (const __half2*)&qb;
#pragma unroll
    for (int c = 0; c < 4; c++) {
        float2 a = __half22float2(kh[c]);
        float2 b = __half22float2(qh[c]);
        acc += a.x * b.x + a.y * b.y;
    }
    g_elog[(size_t)h * N_EDGES + p] = __float2half(__expf(acc));
}

// ---------------- softmax + aggregation: per-et v accumulation, msg applied once per (dst,h,et) ----------------
// Identity: sum_e a_e (v_e @ M_et) = sum_et (sum_{e in et} a_e v_e) @ M_et.
// v gather hits the 12.8MB L2-resident v plane (vs 102MB random vt before).
__global__ void k_agg(const float* __restrict__ msg) {
    int d = blockIdx.x;
    int tid = threadIdx.x;
    int h = tid >> 5;
    int lane = tid & 31;
    int rs = g_rowstart[d];
    int deg = g_rowstart[d + 1] - rs;
    int jg = lane & 7;
    int quad = lane >> 3;
    const __half* el = g_elog + (size_t)h * N_EDGES + rs;

    __shared__ float sPre[NH][TE][DK];   // 4KB

    if (deg == 0) {
        if (lane < 8) ((__half2*)&g_agg_h[d * DHID + h * DK])[jg] = __floats2half2_rn(0.f, 0.f);
        return;
    }
    // pass 1: denom (read-only, fp16 in L2)
    float s = 0.f;
    for (int i = lane; i < deg; i += 32) s += __half2float(el[i]);
#pragma unroll
    for (int o = 16; o > 0; o >>= 1) s += __shfl_xor_sync(0xffffffffu, s, o);
    float inv = 1.f / s;

    // pass 2: per-et weighted v accumulation (predicated registers; no in-loop shuffles)
    const __half* vp = g_kqv_h + (size_t)(2 * NH + h) * N_NODES * DK;
    float accx[TE], accy[TE];
#pragma unroll
    for (int t = 0; t < TE; t++) { accx[t] = 0.f; accy[t] = 0.f; }
    for (int i = quad; i < deg; i += 4) {
        float a = __half2float(el[i]);
        int e = g_eidx[rs + i];
        int et = e >> 16;
        int sn = e & 0xFFFF;
        __half2 v = *((const __half2*)(vp + (size_t)sn * DK) + jg);
        float2 vf = __half22float2(v);
        float wx = a * vf.x;
        float wy = a * vf.y;
#pragma unroll
        for (int t = 0; t < TE; t++) {
            if (et == t) { accx[t] += wx; accy[t] += wy; }
        }
    }
    // reduce across quads (all lanes reconverged -> full-warp shuffles safe)
#pragma unroll
    for (int t = 0; t < TE; t++) {
        accx[t] += __shfl_xor_sync(0xffffffffu, accx[t], 8);
        accx[t] += __shfl_xor_sync(0xffffffffu, accx[t], 16);
        accy[t] += __shfl_xor_sync(0xffffffffu, accy[t], 8);
        accy[t] += __shfl_xor_sync(0xffffffffu, accy[t], 16);
    }
    if (lane < 8) {
#pragma unroll
        for (int t = 0; t < TE; t++) {
            sPre[h][t][jg * 2]     = accx[t] * inv;
            sPre[h][t][jg * 2 + 1] = accy[t] * inv;
        }
    }
    __syncwarp();

    // epilogue: out[j] = sum_et sum_i pre[et][i] * msg[et,h][i][j]
    // lane = et*4 + jq; each lane computes 4 j's for one et, then et-reduce via shfl.
    int et_l = lane >> 2;
    int jq = lane & 3;
    const float* M = msg + (et_l * NH + h) * 256 + jq * 4;
    float o0 = 0.f, o1 = 0.f, o2 = 0.f, o3 = 0.f;
#pragma unroll
    for (int i = 0; i < 16; i++) {
        float p = sPre[h][et_l][i];
        float4 mr = *((const float4*)(M + i * 16));
        o0 += p * mr.x; o1 += p * mr.y; o2 += p * mr.z; o3 += p * mr.w;
    }
#pragma unroll
    for (int o = 4; o < 32; o <<= 1) {
        o0 += __shfl_xor_sync(0xffffffffu, o0, o);
        o1 += __shfl_xor_sync(0xffffffffu, o1, o);
        o2 += __shfl_xor_sync(0xffffffffu, o2, o);
        o3 += __shfl_xor_sync(0xffffffffu, o3, o);
    }
    if (lane < 4) {
        __half2* outp = (__half2*)&g_agg_h[d * DHID + h * DK + jq * 4];
        outp[0] = __floats2half2_rn(o0, o1);
        outp[1] = __floats2half2_rn(o2, o3);
    }
}

// ---------------- output via tensor cores: relu(agg@Wa[t] + x@loop + bias) ----------------
__global__ void k_out(const float* __restrict__ x, const float* __restrict__ bias,
                      float* __restrict__ out) {
    int t = blockIdx.y;
    int cnt = g_tstart[t + 1] - g_tstart[t];
    int tile = blockIdx.x * 64;
    if (tile >= cnt) return;

    __shared__ __align__(16) __half As[64][136];
    __shared__ __align__(16) __half Ws[64][136];
    __shared__ int rows[64];

    int tid = threadIdx.x;
    if (tid < 64) {
        int r = tile + tid;
        rows[tid] = (r < cnt) ? g_node_order[g_tstart[t] + r] : -1;
    }
    __syncthreads();

    int w = tid >> 5;
    int lane = tid & 31;
    int mr = (w & 3) * 16;
    int nc = (w >> 2) * 64;
    int lrow = (lane & 7) + ((lane >> 3) & 1) * 8;
    int lcol8 = (lane >> 4) * 8;
    int r0 = mr + (lane >> 2);
    int cb = nc + (lane & 3) * 2;

    float acc[8][4];
#pragma unroll
    for (int nt = 0; nt < 8; nt++) {
#pragma unroll
        for (int c = 0; c < 4; c++) acc[nt][c] = 0.f;
    }

    for (int ph = 0; ph < 4; ph++) {
        if (ph != 2) {   // phase 2 reuses x_hi from phase 1
            __syncthreads();
            if (ph == 0) {
                for (int i = tid; i < 64 * 16; i += 256) {
                    int r = i >> 4;
                    int c8 = i & 15;
                    uint4 v = make_uint4(0u, 0u, 0u, 0u);
                    int g = rows[r];
                    if (g >= 0) v = ((const uint4*)&g_agg_h[g * DHID])[c8];
                    *((uint4*)&As[r][c8 * 8]) = v;
                }
            } else {
                for (int i = tid; i < 64 * 32; i += 256) {
                    int r = i >> 5;
                    int c4 = i & 31;
                    float4 v = make_float4(0.f, 0.f, 0.f, 0.f);
                    int g = rows[r];
                    if (g >= 0) v = ((const float4*)x)[g * 32 + c4];
                    __half2 h0 = __floats2half2_rn(v.x, v.y);
                    __half2 h1 = __floats2half2_rn(v.z, v.w);
                    if (ph == 3) {   // residual: lo = fp16(x - hi)
                        float2 f0 = __half22float2(h0);
                        float2 f1 = __half22float2(h1);
                        h0 = __floats2half2_rn(v.x - f0.x, v.y - f0.y);
                        h1 = __floats2half2_rn(v.z - f1.x, v.w - f1.y);
                    }
                    *((__half2*)&As[r][c4 * 4])     = h0;
                    *((__half2*)&As[r][c4 * 4 + 2]) = h1;
                }
            }
        }
        const __half* B = (ph == 0) ? (g_W_h + (3 * TN + t) * (DIN * DHID))
                        : (ph == 2) ? g_lw_lo : g_lw_hi;
        for (int kc = 0; kc < 2; kc++) {
            __syncthreads();
            for (int i = tid; i < 64 * 16; i += 256) {
                int r = i >> 4;
                int c8 = i & 15;
                *((uint4*)&Ws[r][c8 * 8]) = ((const uint4*)(B + (kc * 64 + r) * DHID))[c8];
            }
            __syncthreads();
#pragma unroll
            for (int ks = 0; ks < 4; ks++) {
                unsigned a0, a1, a2, a3;
                unsigned aAddr = (unsigned)__cvta_generic_to_shared(
                    &As[mr + lrow][kc * 64 + ks * 16 + lcol8]);
                ldsm_x4(a0, a1, a2, a3, aAddr);
#pragma unroll
                for (int np = 0; np < 4; np++) {
                    unsigned b0, b1, b2, b3;
                    unsigned bAddr = (unsigned)__cvta_generic_to_shared(
                        &Ws[ks * 16 + lrow][nc + np * 16 + lcol8]);
                    ldsm_x4_t(b0, b1, b2, b3, bAddr);
                    mma16816(acc[np * 2],     a0, a1, a2, a3, b0, b1);
                    mma16816(acc[np * 2 + 1], a0, a1, a2, a3, b2, b3);
                }
            }
        }
    }

    int g0 = rows[r0];
    int g1 = rows[r0 + 8];
#pragma unroll
    for (int nt = 0; nt < 8; nt++) {
        int c = cb + nt * 8;
        float2 bv = *((const float2*)&bias[c]);
        if (g0 >= 0) {
            *((float2*)&out[g0 * DHID + c]) =
                make_float2(fmaxf(acc[nt][0] + bv.x, 0.f), fmaxf(acc[nt][1] + bv.y, 0.f));
        }
        if (g1 >= 0) {
            *((float2*)&out[g1 * DHID + c]) =
                make_float2(fmaxf(acc[nt][2] + bv.x, 0.f), fmaxf(acc[nt][3] + bv.y, 0.f));
        }
    }
}

// ---------------- launch ----------------
extern "C" void kernel_launch(void* const* d_in, const int* in_sizes, int n_in,
                              void* d_out, int out_size) {
    const float* x     = (const float*)d_in[0];
    const int*   ntype = (const int*)d_in[1];
    const int*   src   = (const int*)d_in[2];
    const int*   dst   = (const int*)d_in[3];
    const int*   etype = (const int*)d_in[4];
    const float* wck   = (const float*)d_in[5];
    const float* wbk   = (const float*)d_in[6];
    const float* wcq   = (const float*)d_in[7];
    const float* wbq   = (const float*)d_in[8];
    const float* wcv   = (const float*)d_in[9];
    const float* wbv   = (const float*)d_in[10];
    const float* wca   = (const float*)d_in[11];
    const float* wba   = (const float*)d_in[12];
    const float* pri   = (const float*)d_in[13];
    const float* att   = (const float*)d_in[14];
    const float* msg   = (const float*)d_in[15];
    const float* loopw = (const float*)d_in[16];
    const float* bias  = (const float*)d_in[17];
    float* out = (float*)d_out;

    k_init<<<(N_NODES + 255) / 256, 256>>>();
    k_prepW<<<(4 * TN * DIN * DHID + 255) / 256, 256>>>(wck, wbk, wcq, wbq, wcv, wbv, wca, wba);
    k_prepL<<<(DIN * DHID + 255) / 256, 256>>>(loopw);
    k_count<<<(N_EDGES + 255) / 256, 256>>>(ntype, dst);
    k_scanA<<<NCHUNK, 1024>>>();
    k_scanB<<<1, 32>>>();
    k_scanC<<<NCHUNK, 1024>>>();
    k_scatter<<<(N_EDGES + 255) / 256, 256>>>(ntype, src, dst, etype);
    k_proj<<<dim3((N_NODES + 63) / 64, TN), 256>>>(x);
    k_qt<<<dim3((N_NODES + 63) / 64, NH), 256>>>(att, pri);
    k_logits<<<dim3((N_EDGES + 255) / 256, NH), 256>>>();
    k_agg<<<N_NODES, 256>>>(msg);
    k_out<<<dim3((N_NODES + 63) / 64, TN), 256>>>(x, bias, out);
}

// round 16
// speedup vs baseline: 1.5181x; 1.5181x over previous
#include <cuda_runtime.h>
#include <cuda_fp16.h>
#include <cstdint>

#define N_NODES 50000
#define N_EDGES 800000
#define DIN 128
#define DHID 128
#define NH 8
#define DK 16
#define TN 8
#define TE 8
#define NB 4
#define NCHUNK ((N_NODES + 1023) / 1024)

// ---------------- scratch (static device memory; no allocations) ----------------
__device__ __half g_W_h[4 * TN * DIN * DHID];          // fp16 Wk,Wq,Wv,Wa for tensor cores
__device__ __half g_lw_hi[DIN * DHID];                 // loopw fp16 high part
__device__ __half g_lw_lo[DIN * DHID];                 // loopw fp16 residual
__device__ __half g_kqv_h[3 * NH * N_NODES * DK];      // k,q,v fp16 [mat][h][n][16] (38.4 MB)
__device__ __half g_qt_h[(size_t)NH * N_NODES * TE * DK]; // (att@q)*pri*scale fp16 [h][n][et][16]
__device__ __half g_vt_h[(size_t)NH * N_NODES * TE * DK]; // v@msg fp16 [h][n][et][16]
__device__ __half g_elog[(size_t)NH * N_EDGES];        // exp(logit) fp16 [h][p] (12.8MB, L2-resident)
__device__ __half g_agg_h[N_NODES * DHID];             // aggregated messages fp16 [n][128]
__device__ int    g_deg[N_NODES];
__device__ int    g_rowstart[N_NODES + 1];
__device__ int    g_cursor[N_NODES];
__device__ int    g_eidx[N_EDGES];                     // (et<<16)|src, sorted by dst
__device__ int    g_dst_s[N_EDGES];                    // dst, sorted (CSR order)
__device__ int    g_node_order[N_NODES];
__device__ int    g_ncount[TN];
__device__ int    g_tstart[TN + 1];
__device__ int    g_tcur[TN];
__device__ int    g_part[NCHUNK];
__device__ int    g_chunkoff[NCHUNK];

// ---------------- warp-mma helpers ----------------
__device__ __forceinline__ void ldsm_x4(unsigned& r0, unsigned& r1, unsigned& r2, unsigned& r3, unsigned addr) {
    asm volatile("ldmatrix.sync.aligned.m8n8.x4.shared.b16 {%0,%1,%2,%3}, [%4];"
                 : "=r"(r0), "=r"(r1), "=r"(r2), "=r"(r3) : "r"(addr));
}
__device__ __forceinline__ void ldsm_x4_t(unsigned& r0, unsigned& r1, unsigned& r2, unsigned& r3, unsigned addr) {
    asm volatile("ldmatrix.sync.aligned.m8n8.x4.trans.shared.b16 {%0,%1,%2,%3}, [%4];"
                 : "=r"(r0), "=r"(r1), "=r"(r2), "=r"(r3) : "r"(addr));
}
__device__ __forceinline__ void mma16816(float* c, unsigned a0, unsigned a1, unsigned a2, unsigned a3,
                                         unsigned b0, unsigned b1) {
    asm volatile("mma.sync.aligned.m16n8k16.row.col.f32.f16.f16.f32 "
                 "{%0,%1,%2,%3},{%4,%5,%6,%7},{%8,%9},{%0,%1,%2,%3};"
                 : "+f"(c[0]), "+f"(c[1]), "+f"(c[2]), "+f"(c[3])
                 : "r"(a0), "r"(a1), "r"(a2), "r"(a3), "r"(b0), "r"(b1));
}

// ---------------- init: zero counters ----------------
__global__ void k_init() {
    int i = blockIdx.x * blockDim.x + threadIdx.x;
    if (i < N_NODES) g_deg[i] = 0;
    if (i < TN) g_ncount[i] = 0;
}

// ---------------- per-type weights (fp16) + loopw hi/lo split (fused) ----------------
__global__ void k_prepW(const float* __restrict__ ck, const float* __restrict__ bk,
                        const float* __restrict__ cq, const float* __restrict__ bq,
                        const float* __restrict__ cv, const float* __restrict__ bv,
                        const float* __restrict__ ca, const float* __restrict__ ba,
                        const float* __restrict__ loopw) {
    int idx = blockIdx.x * blockDim.x + threadIdx.x;           // 4 * 8 * 16384
    if (idx >= 4 * TN * DIN * DHID) return;
    int m  = idx >> 17;           // matrix id
    int r  = idx & 131071;
    int t  = r >> 14;             // type
    int io = r & 16383;
    const float* comp;
    const float* basis;
    if (m == 0)      { comp = ck; basis = bk; }
    else if (m == 1) { comp = cq; basis = bq; }
    else if (m == 2) { comp = cv; basis = bv; }
    else             { comp = ca; basis = ba; }
    float acc = 0.f;
#pragma unroll
    for (int b = 0; b < NB; b++)
        acc += comp[t * NB + b] * basis[b * (DIN * DHID) + io];
    g_W_h[idx] = __float2half(acc);
    if (idx < DIN * DHID) {
        float w = loopw[idx];
        __half hi = __float2half(w);
        g_lw_hi[idx] = hi;
        g_lw_lo[idx] = __float2half(w - __half2float(hi));
    }
}

// ---------------- counts: node types + in-degrees ----------------
__global__ void k_count(const int* __restrict__ ntype, const int* __restrict__ dst) {
    int i = blockIdx.x * blockDim.x + threadIdx.x;
    if (i < N_NODES) atomicAdd(&g_ncount[ntype[i]], 1);
    if (i < N_EDGES) atomicAdd(&g_deg[dst[i]], 1);
}

// ---------------- parallel scan phase A ----------------
__global__ void k_scanA() {
    __shared__ int wsum[32];
    int tid = threadIdx.x;
    int chunk = blockIdx.x;
    int i = chunk * 1024 + tid;
    int v = (i < N_NODES) ? g_deg[i] : 0;
    int lane = tid & 31, w = tid >> 5;
    int s = v;
#pragma unroll
    for (int o = 1; o < 32; o <<= 1) {
        int t = __shfl_up_sync(0xffffffffu, s, o);
        if (lane >= o) s += t;
    }
    if (lane == 31) wsum[w] = s;
    __syncthreads();
    if (w == 0) {
        int x = wsum[lane];
#pragma unroll
        for (int o = 1; o < 32; o <<= 1) {
            int t = __shfl_up_sync(0xffffffffu, x, o);
            if (lane >= o) x += t;
        }
        wsum[lane] = x;
    }
    __syncthreads();
    int excl = s - v + (w > 0 ? wsum[w - 1] : 0);
    if (i < N_NODES) g_rowstart[i] = excl;
    if (tid == 1023) g_part[chunk] = excl + v;
}

// ---------------- scan phase B ----------------
__global__ void k_scanB() {
    if (threadIdx.x == 0) {
        int acc = 0;
        for (int c = 0; c < NCHUNK; c++) { g_chunkoff[c] = acc; acc += g_part[c]; }
        g_rowstart[N_NODES] = N_EDGES;
        int a2 = 0;
        g_tstart[0] = 0;
        for (int t = 0; t < TN; t++) { a2 += g_ncount[t]; g_tstart[t + 1] = a2; }
        for (int t = 0; t < TN; t++) g_tcur[t] = g_tstart[t];
    }
}

// ---------------- scan phase C ----------------
__global__ void k_scanC() {
    int i = blockIdx.x * 1024 + threadIdx.x;
    if (i < N_NODES) {
        int r = g_rowstart[i] + g_chunkoff[blockIdx.x];
        g_rowstart[i] = r;
        g_cursor[i] = r;
    }
}

// ---------------- scatter ----------------
__global__ void k_scatter(const int* __restrict__ ntype, const int* __restrict__ src,
                          const int* __restrict__ dst, const int* __restrict__ etype) {
    int i = blockIdx.x * blockDim.x + threadIdx.x;
    if (i < N_NODES) {
        int t = ntype[i];
        int p = atomicAdd(&g_tcur[t], 1);
        g_node_order[p] = i;
    }
    if (i < N_EDGES) {
        int d = dst[i];
        int p = atomicAdd(&g_cursor[d], 1);
        g_eidx[p] = (etype[i] << 16) | src[i];    // N_NODES < 65536
        g_dst_s[p] = d;
    }
}

// ---------------- projection GEMM via tensor cores (fp16 in, fp32 accum, fp16 out) ----------------
// tile: 64 nodes x 128 out, K=128 in 2 chunks of 64. 8 warps = 4M x 2N.
__global__ void k_proj(const float* __restrict__ x) {
    int t = blockIdx.y;
    int cnt = g_tstart[t + 1] - g_tstart[t];
    int tile = blockIdx.x * 64;
    if (tile >= cnt) return;

    __shared__ __align__(16) __half As[64][136];
    __shared__ __align__(16) __half Ws[64][136];
    __shared__ int rows[64];

    int tid = threadIdx.x;
    if (tid < 64) {
        int r = tile + tid;
        rows[tid] = (r < cnt) ? g_node_order[g_tstart[t] + r] : -1;
    }
    __syncthreads();

    // gathered x rows -> fp16 smem
    for (int i = tid; i < 64 * 32; i += 256) {
        int nr = i >> 5;
        int c4 = i & 31;
        float4 v = make_float4(0.f, 0.f, 0.f, 0.f);
        int g = rows[nr];
        if (g >= 0) v = ((const float4*)x)[g * 32 + c4];
        *((__half2*)&As[nr][c4 * 4])     = __floats2half2_rn(v.x, v.y);
        *((__half2*)&As[nr][c4 * 4 + 2]) = __floats2half2_rn(v.z, v.w);
    }

    int w = tid >> 5;
    int lane = tid & 31;
    int mr = (w & 3) * 16;            // M offset of this warp
    int nc = (w >> 2) * 64;           // N offset of this warp
    int lrow = (lane & 7) + ((lane >> 3) & 1) * 8;   // ldmatrix source row (within 16)
    int lcol8 = (lane >> 4) * 8;                     // ldmatrix 8-col group

    int r0 = mr + (lane >> 2);        // accumulator row (mma layout)
    int cb = nc + (lane & 3) * 2;     // accumulator col base

    for (int mat = 0; mat < 3; mat++) {
        float acc[8][4];
#pragma unroll
        for (int nt = 0; nt < 8; nt++) {
#pragma unroll
            for (int c = 0; c < 4; c++) acc[nt][c] = 0.f;
        }

        const __half* W = g_W_h + (mat * TN + t) * (DIN * DHID);
        for (int kc = 0; kc < 2; kc++) {
            __syncthreads();   // protects Ws rewrite (and As on first pass)
            for (int i = tid; i < 64 * 16; i += 256) {
                int r = i >> 4;
                int c8 = i & 15;
                *((uint4*)&Ws[r][c8 * 8]) = ((const uint4*)(W + (kc * 64 + r) * DHID))[c8];
            }
            __syncthreads();
#pragma unroll
            for (int ks = 0; ks < 4; ks++) {
                unsigned a0, a1, a2, a3;
                unsigned aAddr = (unsigned)__cvta_generic_to_shared(
                    &As[mr + lrow][kc * 64 + ks * 16 + lcol8]);
                ldsm_x4(a0, a1, a2, a3, aAddr);
#pragma unroll
                for (int np = 0; np < 4; np++) {
                    unsigned b0, b1, b2, b3;
                    unsigned bAddr = (unsigned)__cvta_generic_to_shared(
                        &Ws[ks * 16 + lrow][nc + np * 16 + lcol8]);
                    ldsm_x4_t(b0, b1, b2, b3, bAddr);
                    mma16816(acc[np * 2],     a0, a1, a2, a3, b0, b1);
                    mma16816(acc[np * 2 + 1], a0, a1, a2, a3, b2, b3);
                }
            }
        }
        // store fp16 to [mat][h][n][16]
        int g0 = rows[r0];
        int g1 = rows[r0 + 8];
#pragma unroll
        for (int nt = 0; nt < 8; nt++) {
            int c = cb + nt * 8;
            int h = c >> 4;
            int j = c & 15;
            size_t base = (size_t)(mat * NH + h) * N_NODES;
            if (g0 >= 0) {
                *((__half2*)&g_kqv_h[(base + g0) * DK + j]) = __floats2half2_rn(acc[nt][0], acc[nt][1]);
            }
            if (g1 >= 0) {
                *((__half2*)&g_kqv_h[(base + g1) * DK + j]) = __floats2half2_rn(acc[nt][2], acc[nt][3]);
            }
        }
    }
}

// ---------------- qt & vt via tensor cores (both [h][n][et][16], coalesced stores) ----------------
__global__ void k_qtvt(const float* __restrict__ att, const float* __restrict__ msg,
                       const float* __restrict__ pri) {
    int h = blockIdx.y;
    int tile = blockIdx.x * 64;
    int tid = threadIdx.x;

    __shared__ __align__(16) __half As[64][24];    // 64x16 A tile
    __shared__ __align__(16) __half Bs[16][136];   // 16x128 B tile

    int w = tid >> 5;
    int lane = tid & 31;
    int mr = (w & 3) * 16;
    int nc = (w >> 2) * 64;
    int lrow = (lane & 7) + ((lane >> 3) & 1) * 8;
    int lcol8 = (lane >> 4) * 8;
    int r0 = mr + (lane >> 2);
    int cb = nc + (lane & 3) * 2;

    for (int ph = 0; ph < 2; ph++) {
        __syncthreads();   // protect As/Bs from previous phase's reads
        {
            const __half* src = g_kqv_h + (size_t)((ph == 0 ? 1 : 2) * NH + h) * N_NODES * DK;
            if (tid < 128) {
                int r = tid >> 1;
                int hc = tid & 1;
                int node = tile + r;
                uint4 v = make_uint4(0u, 0u, 0u, 0u);
                if (node < N_NODES) v = *((const uint4*)(src + (size_t)node * DK + hc * 8));
                *((uint4*)&As[r][hc * 8]) = v;
            }
        }
        {
            const float* M = (ph == 0) ? att : msg;
            for (int e = tid; e < 16 * 128; e += 256) {
                int i = e >> 7;
                int c = e & 127;
                int et = c >> 4;
                int j = c & 15;
                float val = M[(et * NH + h) * 256 + i * 16 + j];
                if (ph == 0) val *= pri[et * NH + h] * 0.25f;
                Bs[i][c] = __float2half(val);
            }
        }
        __syncthreads();

        float acc[8][4];
#pragma unroll
        for (int nt = 0; nt < 8; nt++) {
#pragma unroll
            for (int c = 0; c < 4; c++) acc[nt][c] = 0.f;
        }
        unsigned a0, a1, a2, a3;
        unsigned aAddr = (unsigned)__cvta_generic_to_shared(&As[mr + lrow][lcol8]);
        ldsm_x4(a0, a1, a2, a3, aAddr);
#pragma unroll
        for (int np = 0; np < 4; np++) {
            unsigned b0, b1, b2, b3;
            unsigned bAddr = (unsigned)__cvta_generic_to_shared(&Bs[lrow][nc + np * 16 + lcol8]);
            ldsm_x4_t(b0, b1, b2, b3, bAddr);
            mma16816(acc[np * 2],     a0, a1, a2, a3, b0, b1);
            mma16816(acc[np * 2 + 1], a0, a1, a2, a3, b2, b3);
        }

        __half* outb = (ph == 0) ? g_qt_h : g_vt_h;
        int n0 = tile + r0;
        int n1 = tile + r0 + 8;
#pragma unroll
        for (int nt = 0; nt < 8; nt++) {
            int c = cb + nt * 8;
            if (n0 < N_NODES) {
                *((__half2*)&outb[((size_t)h * N_NODES + n0) * 128 + c]) =
                    __floats2half2_rn(acc[nt][0], acc[nt][1]);
            }
            if (n1 < N_NODES) {
                *((__half2*)&outb[((size_t)h * N_NODES + n1) * 128 + c]) =
                    __floats2half2_rn(acc[nt][2], acc[nt][3]);
            }
        }
    }
}

// ---------------- edge attention: exp(logit) directly (|logit| << 1, max-shift unnecessary) ----------------
__global__ void k_logits() {
    int p = blockIdx.x * blockDim.x + threadIdx.x;
    int h = blockIdx.y;
    if (p >= N_EDGES) return;
    int e = g_eidx[p];
    int et = e >> 16;
    int s = e & 0xFFFF;
    int d = g_dst_s[p];
    const uint4* kk4 = (const uint4*)(g_kqv_h + ((size_t)h * N_NODES + s) * DK);
    const uint4* qt4 = (const uint4*)(g_qt_h + ((size_t)h * N_NODES + d) * 128 + et * DK);
    uint4 ka = kk4[0], kb = kk4[1];
    uint4 qa = qt4[0], qb = qt4[1];
    const __half2* kh = (const __half2*)&ka;
    const __half2* qh = (const __half2*)&qa;
    float acc = 0.f;
#pragma unroll
    for (int c = 0; c < 4; c++) {
        float2 a = __half22float2(kh[c]);
        float2 b = __half22float2(qh[c]);
        acc += a.x * b.x + a.y * b.y;
    }
    kh = (const __half2*)&kb;
    qh = (const __half2*)&qb;
#pragma unroll
    for (int c = 0; c < 4; c++) {
        float2 a = __half22float2(kh[c]);
        float2 b = __half22float2(qh[c]);
        acc += a.x * b.x + a.y * b.y;
    }
    g_elog[(size_t)h * N_EDGES + p] = __float2half(__expf(acc));
}

// ---------------- edge softmax + aggregation (elog L2-resident; 4 edges in flight) ----------------
__global__ void k_agg() {
    int d = blockIdx.x;
    int h = threadIdx.x >> 5;
    int lane = threadIdx.x & 31;
    int rs = g_rowstart[d];
    int deg = g_rowstart[d + 1] - rs;
    int j2 = lane & 7;
    int quad = lane >> 3;
    const __half* el = g_elog + (size_t)h * N_EDGES + rs;

    if (deg == 0) {
        if (lane < 8) ((__half2*)&g_agg_h[d * DHID + h * DK])[j2] = __floats2half2_rn(0.f, 0.f);
        return;
    }
    // pass 1: denom (read-only, fp16 in L2)
    float s = 0.f;
#pragma unroll 2
    for (int i = lane; i < deg; i += 32) s += __half2float(el[i]);
#pragma unroll
    for (int o = 16; o > 0; o >>= 1) s += __shfl_xor_sync(0xffffffffu, s, o);
    float inv = 1.f / s;
    // pass 2: weighted vt gather (4 edges in flight x unroll 2; each lane covers 2 j's)
    float ax = 0.f, ay = 0.f;
#pragma unroll 2
    for (int i = quad; i < deg; i += 4) {
        float a = __half2float(el[i]);
        int e = g_eidx[rs + i];
        int et = e >> 16;
        int sn = e & 0xFFFF;
        __half2 v = *((const __half2*)(g_vt_h + ((size_t)h * N_NODES + sn) * 128 + et * DK) + j2);
        float2 vf = __half22float2(v);
        ax += a * vf.x;
        ay += a * vf.y;
    }
#pragma unroll
    for (int o = 16; o >= 8; o >>= 1) {
        ax += __shfl_xor_sync(0xffffffffu, ax, o);
        ay += __shfl_xor_sync(0xffffffffu, ay, o);
    }
    if (lane < 8) ((__half2*)&g_agg_h[d * DHID + h * DK])[j2] = __floats2half2_rn(ax * inv, ay * inv);
}

// ---------------- output via tensor cores: relu(agg@Wa[t] + x@loop + bias) ----------------
__global__ void k_out(const float* __restrict__ x, const float* __restrict__ bias,
                      float* __restrict__ out) {
    int t = blockIdx.y;
    int cnt = g_tstart[t + 1] - g_tstart[t];
    int tile = blockIdx.x * 64;
    if (tile >= cnt) return;

    __shared__ __align__(16) __half As[64][136];
    __shared__ __align__(16) __half Ws[64][136];
    __shared__ int rows[64];

    int tid = threadIdx.x;
    if (tid < 64) {
        int r = tile + tid;
        rows[tid] = (r < cnt) ? g_node_order[g_tstart[t] + r] : -1;
    }
    __syncthreads();

    int w = tid >> 5;
    int lane = tid & 31;
    int mr = (w & 3) * 16;
    int nc = (w >> 2) * 64;
    int lrow = (lane & 7) + ((lane >> 3) & 1) * 8;
    int lcol8 = (lane >> 4) * 8;
    int r0 = mr + (lane >> 2);
    int cb = nc + (lane & 3) * 2;

    float acc[8][4];
#pragma unroll
    for (int nt = 0; nt < 8; nt++) {
#pragma unroll
        for (int c = 0; c < 4; c++) acc[nt][c] = 0.f;
    }

    for (int ph = 0; ph < 4; ph++) {
        if (ph != 2) {   // phase 2 reuses x_hi from phase 1
            __syncthreads();
            if (ph == 0) {
                for (int i = tid; i < 64 * 16; i += 256) {
                    int r = i >> 4;
                    int c8 = i & 15;
                    uint4 v = make_uint4(0u, 0u, 0u, 0u);
                    int g = rows[r];
                    if (g >= 0) v = ((const uint4*)&g_agg_h[g * DHID])[c8];
                    *((uint4*)&As[r][c8 * 8]) = v;
                }
            } else {
                for (int i = tid; i < 64 * 32; i += 256) {
                    int r = i >> 5;
                    int c4 = i & 31;
                    float4 v = make_float4(0.f, 0.f, 0.f, 0.f);
                    int g = rows[r];
                    if (g >= 0) v = ((const float4*)x)[g * 32 + c4];
                    __half2 h0 = __floats2half2_rn(v.x, v.y);
                    __half2 h1 = __floats2half2_rn(v.z, v.w);
                    if (ph == 3) {   // residual: lo = fp16(x - hi)
                        float2 f0 = __half22float2(h0);
                        float2 f1 = __half22float2(h1);
                        h0 = __floats2half2_rn(v.x - f0.x, v.y - f0.y);
                        h1 = __floats2half2_rn(v.z - f1.x, v.w - f1.y);
                    }
                    *((__half2*)&As[r][c4 * 4])     = h0;
                    *((__half2*)&As[r][c4 * 4 + 2]) = h1;
                }
            }
        }
        const __half* B = (ph == 0) ? (g_W_h + (3 * TN + t) * (DIN * DHID))
                        : (ph == 2) ? g_lw_lo : g_lw_hi;
        for (int kc = 0; kc < 2; kc++) {
            __syncthreads();
            for (int i = tid; i < 64 * 16; i += 256) {
                int r = i >> 4;
                int c8 = i & 15;
                *((uint4*)&Ws[r][c8 * 8]) = ((const uint4*)(B + (kc * 64 + r) * DHID))[c8];
            }
            __syncthreads();
#pragma unroll
            for (int ks = 0; ks < 4; ks++) {
                unsigned a0, a1, a2, a3;
                unsigned aAddr = (unsigned)__cvta_generic_to_shared(
                    &As[mr + lrow][kc * 64 + ks * 16 + lcol8]);
                ldsm_x4(a0, a1, a2, a3, aAddr);
#pragma unroll
                for (int np = 0; np < 4; np++) {
                    unsigned b0, b1, b2, b3;
                    unsigned bAddr = (unsigned)__cvta_generic_to_shared(
                        &Ws[ks * 16 + lrow][nc + np * 16 + lcol8]);
                    ldsm_x4_t(b0, b1, b2, b3, bAddr);
                    mma16816(acc[np * 2],     a0, a1, a2, a3, b0, b1);
                    mma16816(acc[np * 2 + 1], a0, a1, a2, a3, b2, b3);
                }
            }
        }
    }

    int g0 = rows[r0];
    int g1 = rows[r0 + 8];
#pragma unroll
    for (int nt = 0; nt < 8; nt++) {
        int c = cb + nt * 8;
        float2 bv = *((const float2*)&bias[c]);
        if (g0 >= 0) {
            *((float2*)&out[g0 * DHID + c]) =
                make_float2(fmaxf(acc[nt][0] + bv.x, 0.f), fmaxf(acc[nt][1] + bv.y, 0.f));
        }
        if (g1 >= 0) {
            *((float2*)&out[g1 * DHID + c]) =
                make_float2(fmaxf(acc[nt][2] + bv.x, 0.f), fmaxf(acc[nt][3] + bv.y, 0.f));
        }
    }
}

// ---------------- launch ----------------
extern "C" void kernel_launch(void* const* d_in, const int* in_sizes, int n_in,
                              void* d_out, int out_size) {
    const float* x     = (const float*)d_in[0];
    const int*   ntype = (const int*)d_in[1];
    const int*   src   = (const int*)d_in[2];
    const int*   dst   = (const int*)d_in[3];
    const int*   etype = (const int*)d_in[4];
    const float* wck   = (const float*)d_in[5];
    const float* wbk   = (const float*)d_in[6];
    const float* wcq   = (const float*)d_in[7];
    const float* wbq   = (const float*)d_in[8];
    const float* wcv   = (const float*)d_in[9];
    const float* wbv   = (const float*)d_in[10];
    const float* wca   = (const float*)d_in[11];
    const float* wba   = (const float*)d_in[12];
    const float* pri   = (const float*)d_in[13];
    const float* att   = (const float*)d_in[14];
    const float* msg   = (const float*)d_in[15];
    const float* loopw = (const float*)d_in[16];
    const float* bias  = (const float*)d_in[17];
    float* out = (float*)d_out;

    k_init<<<(N_NODES + 255) / 256, 256>>>();
    k_prepW<<<(4 * TN * DIN * DHID + 255) / 256, 256>>>(wck, wbk, wcq, wbq, wcv, wbv, wca, wba, loopw);
    k_count<<<(N_EDGES + 255) / 256, 256>>>(ntype, dst);
    k_scanA<<<NCHUNK, 1024>>>();
    k_scanB<<<1, 32>>>();
    k_scanC<<<NCHUNK, 1024>>>();
    k_scatter<<<(N_EDGES + 255) / 256, 256>>>(ntype, src, dst, etype);
    k_proj<<<dim3((N_NODES + 63) / 64, TN), 256>>>(x);
    k_qtvt<<<dim3((N_NODES + 63) / 64, NH), 256>>>(att, msg, pri);
    k_logits<<<dim3((N_EDGES + 255) / 256, NH), 256>>>();
    k_agg<<<N_NODES, 256>>>();
    k_out<<<dim3((N_NODES + 63) / 64, TN), 256>>>(x, bias, out);
}

// round 17
// speedup vs baseline: 1.5350x; 1.0112x over previous
#include <cuda_runtime.h>
#include <cuda_fp16.h>
#include <cstdint>

#define N_NODES 50000
#define N_EDGES 800000
#define DIN 128
#define DHID 128
#define NH 8
#define DK 16
#define TN 8
#define TE 8
#define NB 4
#define NCHUNK ((N_NODES + 1023) / 1024)

// ---------------- scratch (static device memory; no allocations) ----------------
__device__ __half g_W_h[4 * TN * DIN * DHID];          // fp16 Wk,Wq,Wv,Wa for tensor cores
__device__ __half g_lw_hi[DIN * DHID];                 // loopw fp16 high part
__device__ __half g_lw_lo[DIN * DHID];                 // loopw fp16 residual
__device__ __half g_kqv_h[3 * NH * N_NODES * DK];      // k,q,v fp16 [mat][h][n][16] (38.4 MB)
__device__ __half g_qt_h[(size_t)NH * N_NODES * TE * DK]; // (att@q)*pri*scale fp16 [h][n][et][16]
__device__ __half g_vt_h[(size_t)NH * N_NODES * TE * DK]; // v@msg fp16 [h][n][et][16]
__device__ __half g_elog[(size_t)NH * N_EDGES];        // exp(logit) fp16 [h][p] (12.8MB, L2-resident)
__device__ __half g_agg_h[N_NODES * DHID];             // aggregated messages fp16 [n][128]
__device__ int    g_deg[N_NODES];
__device__ int    g_rowstart[N_NODES + 1];
__device__ int    g_cursor[N_NODES];
__device__ int    g_eidx[N_EDGES];                     // (et<<16)|src, sorted by dst
__device__ int    g_dst_s[N_EDGES];                    // dst, sorted (CSR order)
__device__ int    g_node_order[N_NODES];
__device__ int    g_ncount[TN];
__device__ int    g_tstart[TN + 1];
__device__ int    g_tcur[TN];
__device__ int    g_part[NCHUNK];
__device__ int    g_chunkoff[NCHUNK];

// ---------------- warp-mma helpers ----------------
__device__ __forceinline__ void ldsm_x4(unsigned& r0, unsigned& r1, unsigned& r2, unsigned& r3, unsigned addr) {
    asm volatile("ldmatrix.sync.aligned.m8n8.x4.shared.b16 {%0,%1,%2,%3}, [%4];"
                 : "=r"(r0), "=r"(r1), "=r"(r2), "=r"(r3) : "r"(addr));
}
__device__ __forceinline__ void ldsm_x4_t(unsigned& r0, unsigned& r1, unsigned& r2, unsigned& r3, unsigned addr) {
    asm volatile("ldmatrix.sync.aligned.m8n8.x4.trans.shared.b16 {%0,%1,%2,%3}, [%4];"
                 : "=r"(r0), "=r"(r1), "=r"(r2), "=r"(r3) : "r"(addr));
}
__device__ __forceinline__ void mma16816(float* c, unsigned a0, unsigned a1, unsigned a2, unsigned a3,
                                         unsigned b0, unsigned b1) {
    asm volatile("mma.sync.aligned.m16n8k16.row.col.f32.f16.f16.f32 "
                 "{%0,%1,%2,%3},{%4,%5,%6,%7},{%8,%9},{%0,%1,%2,%3};"
                 : "+f"(c[0]), "+f"(c[1]), "+f"(c[2]), "+f"(c[3])
                 : "r"(a0), "r"(a1), "r"(a2), "r"(a3), "r"(b0), "r"(b1));
}

// ---------------- init: zero counters ----------------
__global__ void k_init() {
    int i = blockIdx.x * blockDim.x + threadIdx.x;
    if (i < N_NODES) g_deg[i] = 0;
    if (i < TN) g_ncount[i] = 0;
}

// ---------------- per-type weights (fp16) + loopw hi/lo split (fused) ----------------
__global__ void k_prepW(const float* __restrict__ ck, const float* __restrict__ bk,
                        const float* __restrict__ cq, const float* __restrict__ bq,
                        const float* __restrict__ cv, const float* __restrict__ bv,
                        const float* __restrict__ ca, const float* __restrict__ ba,
                        const float* __restrict__ loopw) {
    int idx = blockIdx.x * blockDim.x + threadIdx.x;           // 4 * 8 * 16384
    if (idx >= 4 * TN * DIN * DHID) return;
    int m  = idx >> 17;           // matrix id
    int r  = idx & 131071;
    int t  = r >> 14;             // type
    int io = r & 16383;
    const float* comp;
    const float* basis;
    if (m == 0)      { comp = ck; basis = bk; }
    else if (m == 1) { comp = cq; basis = bq; }
    else if (m == 2) { comp = cv; basis = bv; }
    else             { comp = ca; basis = ba; }
    float acc = 0.f;
#pragma unroll
    for (int b = 0; b < NB; b++)
        acc += comp[t * NB + b] * basis[b * (DIN * DHID) + io];
    g_W_h[idx] = __float2half(acc);
    if (idx < DIN * DHID) {
        float w = loopw[idx];
        __half hi = __float2half(w);
        g_lw_hi[idx] = hi;
        g_lw_lo[idx] = __float2half(w - __half2float(hi));
    }
}

// ---------------- counts: node types + in-degrees ----------------
__global__ void k_count(const int* __restrict__ ntype, const int* __restrict__ dst) {
    int i = blockIdx.x * blockDim.x + threadIdx.x;
    if (i < N_NODES) atomicAdd(&g_ncount[ntype[i]], 1);
    if (i < N_EDGES) atomicAdd(&g_deg[dst[i]], 1);
}

// ---------------- parallel scan phase A ----------------
__global__ void k_scanA() {
    __shared__ int wsum[32];
    int tid = threadIdx.x;
    int chunk = blockIdx.x;
    int i = chunk * 1024 + tid;
    int v = (i < N_NODES) ? g_deg[i] : 0;
    int lane = tid & 31, w = tid >> 5;
    int s = v;
#pragma unroll
    for (int o = 1; o < 32; o <<= 1) {
        int t = __shfl_up_sync(0xffffffffu, s, o);
        if (lane >= o) s += t;
    }
    if (lane == 31) wsum[w] = s;
    __syncthreads();
    if (w == 0) {
        int x = wsum[lane];
#pragma unroll
        for (int o = 1; o < 32; o <<= 1) {
            int t = __shfl_up_sync(0xffffffffu, x, o);
            if (lane >= o) x += t;
        }
        wsum[lane] = x;
    }
    __syncthreads();
    int excl = s - v + (w > 0 ? wsum[w - 1] : 0);
    if (i < N_NODES) g_rowstart[i] = excl;
    if (tid == 1023) g_part[chunk] = excl + v;
}

// ---------------- scan phase B ----------------
__global__ void k_scanB() {
    if (threadIdx.x == 0) {
        int acc = 0;
        for (int c = 0; c < NCHUNK; c++) { g_chunkoff[c] = acc; acc += g_part[c]; }
        g_rowstart[N_NODES] = N_EDGES;
        int a2 = 0;
        g_tstart[0] = 0;
        for (int t = 0; t < TN; t++) { a2 += g_ncount[t]; g_tstart[t + 1] = a2; }
        for (int t = 0; t < TN; t++) g_tcur[t] = g_tstart[t];
    }
}

// ---------------- scan phase C ----------------
__global__ void k_scanC() {
    int i = blockIdx.x * 1024 + threadIdx.x;
    if (i < N_NODES) {
        int r = g_rowstart[i] + g_chunkoff[blockIdx.x];
        g_rowstart[i] = r;
        g_cursor[i] = r;
    }
}

// ---------------- scatter ----------------
__global__ void k_scatter(const int* __restrict__ ntype, const int* __restrict__ src,
                          const int* __restrict__ dst, const int* __restrict__ etype) {
    int i = blockIdx.x * blockDim.x + threadIdx.x;
    if (i < N_NODES) {
        int t = ntype[i];
        int p = atomicAdd(&g_tcur[t], 1);
        g_node_order[p] = i;
    }
    if (i < N_EDGES) {
        int d = dst[i];
        int p = atomicAdd(&g_cursor[d], 1);
        g_eidx[p] = (etype[i] << 16) | src[i];    // N_NODES < 65536
        g_dst_s[p] = d;
    }
}

// ---------------- projection GEMM via tensor cores (fp16 in, fp32 accum, fp16 out) ----------------
// tile: 64 nodes x 128 out, K=128 in 2 chunks of 64. 8 warps = 4M x 2N.
__global__ void k_proj(const float* __restrict__ x) {
    int t = blockIdx.y;
    int cnt = g_tstart[t + 1] - g_tstart[t];
    int tile = blockIdx.x * 64;
    if (tile >= cnt) return;

    __shared__ __align__(16) __half As[64][136];
    __shared__ __align__(16) __half Ws[64][136];
    __shared__ int rows[64];

    int tid = threadIdx.x;
    if (tid < 64) {
        int r = tile + tid;
        rows[tid] = (r < cnt) ? g_node_order[g_tstart[t] + r] : -1;
    }
    __syncthreads();

    // gathered x rows -> fp16 smem
    for (int i = tid; i < 64 * 32; i += 256) {
        int nr = i >> 5;
        int c4 = i & 31;
        float4 v = make_float4(0.f, 0.f, 0.f, 0.f);
        int g = rows[nr];
        if (g >= 0) v = ((const float4*)x)[g * 32 + c4];
        *((__half2*)&As[nr][c4 * 4])     = __floats2half2_rn(v.x, v.y);
        *((__half2*)&As[nr][c4 * 4 + 2]) = __floats2half2_rn(v.z, v.w);
    }

    int w = tid >> 5;
    int lane = tid & 31;
    int mr = (w & 3) * 16;            // M offset of this warp
    int nc = (w >> 2) * 64;           // N offset of this warp
    int lrow = (lane & 7) + ((lane >> 3) & 1) * 8;   // ldmatrix source row (within 16)
    int lcol8 = (lane >> 4) * 8;                     // ldmatrix 8-col group

    int r0 = mr + (lane >> 2);        // accumulator row (mma layout)
    int cb = nc + (lane & 3) * 2;     // accumulator col base

    for (int mat = 0; mat < 3; mat++) {
        float acc[8][4];
#pragma unroll
        for (int nt = 0; nt < 8; nt++) {
#pragma unroll
            for (int c = 0; c < 4; c++) acc[nt][c] = 0.f;
        }

        const __half* W = g_W_h + (mat * TN + t) * (DIN * DHID);
        for (int kc = 0; kc < 2; kc++) {
            __syncthreads();   // protects Ws rewrite (and As on first pass)
            for (int i = tid; i < 64 * 16; i += 256) {
                int r = i >> 4;
                int c8 = i & 15;
                *((uint4*)&Ws[r][c8 * 8]) = ((const uint4*)(W + (kc * 64 + r) * DHID))[c8];
            }
            __syncthreads();
#pragma unroll
            for (int ks = 0; ks < 4; ks++) {
                unsigned a0, a1, a2, a3;
                unsigned aAddr = (unsigned)__cvta_generic_to_shared(
                    &As[mr + lrow][kc * 64 + ks * 16 + lcol8]);
                ldsm_x4(a0, a1, a2, a3, aAddr);
#pragma unroll
                for (int np = 0; np < 4; np++) {
                    unsigned b0, b1, b2, b3;
                    unsigned bAddr = (unsigned)__cvta_generic_to_shared(
                        &Ws[ks * 16 + lrow][nc + np * 16 + lcol8]);
                    ldsm_x4_t(b0, b1, b2, b3, bAddr);
                    mma16816(acc[np * 2],     a0, a1, a2, a3, b0, b1);
                    mma16816(acc[np * 2 + 1], a0, a1, a2, a3, b2, b3);
                }
            }
        }
        // store fp16 to [mat][h][n][16]
        int g0 = rows[r0];
        int g1 = rows[r0 + 8];
#pragma unroll
        for (int nt = 0; nt < 8; nt++) {
            int c = cb + nt * 8;
            int h = c >> 4;
            int j = c & 15;
            size_t base = (size_t)(mat * NH + h) * N_NODES;
            if (g0 >= 0) {
                *((__half2*)&g_kqv_h[(base + g0) * DK + j]) = __floats2half2_rn(acc[nt][0], acc[nt][1]);
            }
            if (g1 >= 0) {
                *((__half2*)&g_kqv_h[(base + g1) * DK + j]) = __floats2half2_rn(acc[nt][2], acc[nt][3]);
            }
        }
    }
}

// ---------------- qt & vt via tensor cores (both [h][n][et][16], coalesced stores) ----------------
__global__ void k_qtvt(const float* __restrict__ att, const float* __restrict__ msg,
                       const float* __restrict__ pri) {
    int h = blockIdx.y;
    int tile = blockIdx.x * 64;
    int tid = threadIdx.x;

    __shared__ __align__(16) __half As[64][24];    // 64x16 A tile
    __shared__ __align__(16) __half Bs[16][136];   // 16x128 B tile

    int w = tid >> 5;
    int lane = tid & 31;
    int mr = (w & 3) * 16;
    int nc = (w >> 2) * 64;
    int lrow = (lane & 7) + ((lane >> 3) & 1) * 8;
    int lcol8 = (lane >> 4) * 8;
    int r0 = mr + (lane >> 2);
    int cb = nc + (lane & 3) * 2;

    for (int ph = 0; ph < 2; ph++) {
        __syncthreads();   // protect As/Bs from previous phase's reads
        {
            const __half* src = g_kqv_h + (size_t)((ph == 0 ? 1 : 2) * NH + h) * N_NODES * DK;
            if (tid < 128) {
                int r = tid >> 1;
                int hc = tid & 1;
                int node = tile + r;
                uint4 v = make_uint4(0u, 0u, 0u, 0u);
                if (node < N_NODES) v = *((const uint4*)(src + (size_t)node * DK + hc * 8));
                *((uint4*)&As[r][hc * 8]) = v;
            }
        }
        {
            const float* M = (ph == 0) ? att : msg;
            for (int e = tid; e < 16 * 128; e += 256) {
                int i = e >> 7;
                int c = e & 127;
                int et = c >> 4;
                int j = c & 15;
                float val = M[(et * NH + h) * 256 + i * 16 + j];
                if (ph == 0) val *= pri[et * NH + h] * 0.25f;
                Bs[i][c] = __float2half(val);
            }
        }
        __syncthreads();

        float acc[8][4];
#pragma unroll
        for (int nt = 0; nt < 8; nt++) {
#pragma unroll
            for (int c = 0; c < 4; c++) acc[nt][c] = 0.f;
        }
        unsigned a0, a1, a2, a3;
        unsigned aAddr = (unsigned)__cvta_generic_to_shared(&As[mr + lrow][lcol8]);
        ldsm_x4(a0, a1, a2, a3, aAddr);
#pragma unroll
        for (int np = 0; np < 4; np++) {
            unsigned b0, b1, b2, b3;
            unsigned bAddr = (unsigned)__cvta_generic_to_shared(&Bs[lrow][nc + np * 16 + lcol8]);
            ldsm_x4_t(b0, b1, b2, b3, bAddr);
            mma16816(acc[np * 2],     a0, a1, a2, a3, b0, b1);
            mma16816(acc[np * 2 + 1], a0, a1, a2, a3, b2, b3);
        }

        __half* outb = (ph == 0) ? g_qt_h : g_vt_h;
        int n0 = tile + r0;
        int n1 = tile + r0 + 8;
#pragma unroll
        for (int nt = 0; nt < 8; nt++) {
            int c = cb + nt * 8;
            if (n0 < N_NODES) {
                *((__half2*)&outb[((size_t)h * N_NODES + n0) * 128 + c]) =
                    __floats2half2_rn(acc[nt][0], acc[nt][1]);
            }
            if (n1 < N_NODES) {
                *((__half2*)&outb[((size_t)h * N_NODES + n1) * 128 + c]) =
                    __floats2half2_rn(acc[nt][2], acc[nt][3]);
            }
        }
    }
}

// ---------------- edge attention: half2 HFMA2 dot, exp(logit) directly ----------------
__global__ void k_logits() {
    int p = blockIdx.x * blockDim.x + threadIdx.x;
    int h = blockIdx.y;
    if (p >= N_EDGES) return;
    int e = g_eidx[p];
    int et = e >> 16;
    int s = e & 0xFFFF;
    int d = g_dst_s[p];
    const uint4* kk4 = (const uint4*)(g_kqv_h + ((size_t)h * N_NODES + s) * DK);
    const uint4* qt4 = (const uint4*)(g_qt_h + ((size_t)h * N_NODES + d) * 128 + et * DK);
    uint4 ka = kk4[0], kb = kk4[1];
    uint4 qa = qt4[0], qb = qt4[1];
    const __half2* kh0 = (const __half2*)&ka;
    const __half2* qh0 = (const __half2*)&qa;
    const __half2* kh1 = (const __half2*)&kb;
    const __half2* qh1 = (const __half2*)&qb;
    __half2 acc2 = __floats2half2_rn(0.f, 0.f);
#pragma unroll
    for (int c = 0; c < 4; c++) acc2 = __hfma2(kh0[c], qh0[c], acc2);
#pragma unroll
    for (int c = 0; c < 4; c++) acc2 = __hfma2(kh1[c], qh1[c], acc2);
    float2 f = __half22float2(acc2);
    g_elog[(size_t)h * N_EDGES + p] = __float2half(__expf(f.x + f.y));
}

// ---------------- edge softmax + aggregation (elog L2-resident; 4 edges in flight) ----------------
__global__ void k_agg() {
    int d = blockIdx.x;
    int h = threadIdx.x >> 5;
    int lane = threadIdx.x & 31;
    int rs = g_rowstart[d];
    int deg = g_rowstart[d + 1] - rs;
    int j2 = lane & 7;
    int quad = lane >> 3;
    const __half* el = g_elog + (size_t)h * N_EDGES + rs;

    if (deg == 0) {
        if (lane < 8) ((__half2*)&g_agg_h[d * DHID + h * DK])[j2] = __floats2half2_rn(0.f, 0.f);
        return;
    }
    // pass 1: denom (read-only, fp16 in L2)
    float s = 0.f;
#pragma unroll 2
    for (int i = lane; i < deg; i += 32) s += __half2float(el[i]);
#pragma unroll
    for (int o = 16; o > 0; o >>= 1) s += __shfl_xor_sync(0xffffffffu, s, o);
    float inv = 1.f / s;
    // pass 2: weighted vt gather (4 edges in flight x unroll 2; each lane covers 2 j's)
    float ax = 0.f, ay = 0.f;
#pragma unroll 2
    for (int i = quad; i < deg; i += 4) {
        float a = __half2float(el[i]);
        int e = g_eidx[rs + i];
        int et = e >> 16;
        int sn = e & 0xFFFF;
        __half2 v = *((const __half2*)(g_vt_h + ((size_t)h * N_NODES + sn) * 128 + et * DK) + j2);
        float2 vf = __half22float2(v);
        ax += a * vf.x;
        ay += a * vf.y;
    }
#pragma unroll
    for (int o = 16; o >= 8; o >>= 1) {
        ax += __shfl_xor_sync(0xffffffffu, ax, o);
        ay += __shfl_xor_sync(0xffffffffu, ay, o);
    }
    if (lane < 8) ((__half2*)&g_agg_h[d * DHID + h * DK])[j2] = __floats2half2_rn(ax * inv, ay * inv);
}

// ---------------- output via tensor cores: relu(agg@Wa[t] + x@loop + bias) ----------------
// phases: 0:(agg,Wa) 1:(x_hi,lw_hi) 2:(x_hi,lw_lo) 3:(x_lo,lw_hi); x_lo cached in smem at ph1.
__global__ void k_out(const float* __restrict__ x, const float* __restrict__ bias,
                      float* __restrict__ out) {
    int t = blockIdx.y;
    int cnt = g_tstart[t + 1] - g_tstart[t];
    int tile = blockIdx.x * 64;
    if (tile >= cnt) return;

    __shared__ __align__(16) __half As[64][136];
    __shared__ __align__(16) __half Xlo[64][136];
    __shared__ __align__(16) __half Ws[64][136];
    __shared__ int rows[64];

    int tid = threadIdx.x;
    if (tid < 64) {
        int r = tile + tid;
        rows[tid] = (r < cnt) ? g_node_order[g_tstart[t] + r] : -1;
    }
    __syncthreads();

    int w = tid >> 5;
    int lane = tid & 31;
    int mr = (w & 3) * 16;
    int nc = (w >> 2) * 64;
    int lrow = (lane & 7) + ((lane >> 3) & 1) * 8;
    int lcol8 = (lane >> 4) * 8;
    int r0 = mr + (lane >> 2);
    int cb = nc + (lane & 3) * 2;

    float acc[8][4];
#pragma unroll
    for (int nt = 0; nt < 8; nt++) {
#pragma unroll
        for (int c = 0; c < 4; c++) acc[nt][c] = 0.f;
    }

    for (int ph = 0; ph < 4; ph++) {
        if (ph < 2) {   // ph2 reuses x_hi (As); ph3 uses Xlo via base switch
            __syncthreads();
            if (ph == 0) {
                for (int i = tid; i < 64 * 16; i += 256) {
                    int r = i >> 4;
                    int c8 = i & 15;
                    uint4 v = make_uint4(0u, 0u, 0u, 0u);
                    int g = rows[r];
                    if (g >= 0) v = ((const uint4*)&g_agg_h[g * DHID])[c8];
                    *((uint4*)&As[r][c8 * 8]) = v;
                }
            } else {
                // load x once; write hi into As and lo into Xlo
                for (int i = tid; i < 64 * 32; i += 256) {
                    int r = i >> 5;
                    int c4 = i & 31;
                    float4 v = make_float4(0.f, 0.f, 0.f, 0.f);
                    int g = rows[r];
                    if (g >= 0) v = ((const float4*)x)[g * 32 + c4];
                    __half2 h0 = __floats2half2_rn(v.x, v.y);
                    __half2 h1 = __floats2half2_rn(v.z, v.w);
                    float2 f0 = __half22float2(h0);
                    float2 f1 = __half22float2(h1);
                    __half2 l0 = __floats2half2_rn(v.x - f0.x, v.y - f0.y);
                    __half2 l1 = __floats2half2_rn(v.z - f1.x, v.w - f1.y);
                    *((__half2*)&As[r][c4 * 4])      = h0;
                    *((__half2*)&As[r][c4 * 4 + 2])  = h1;
                    *((__half2*)&Xlo[r][c4 * 4])     = l0;
                    *((__half2*)&Xlo[r][c4 * 4 + 2]) = l1;
                }
            }
        }
        const __half (*Asrc)[136] = (ph == 3) ? Xlo : As;
        const __half* B = (ph == 0) ? (g_W_h + (3 * TN + t) * (DIN * DHID))
                        : (ph == 2) ? g_lw_lo : g_lw_hi;
        for (int kc = 0; kc < 2; kc++) {
            __syncthreads();
            for (int i = tid; i < 64 * 16; i += 256) {
                int r = i >> 4;
                int c8 = i & 15;
                *((uint4*)&Ws[r][c8 * 8]) = ((const uint4*)(B + (kc * 64 + r) * DHID))[c8];
            }
            __syncthreads();
#pragma unroll
            for (int ks = 0; ks < 4; ks++) {
                unsigned a0, a1, a2, a3;
                unsigned aAddr = (unsigned)__cvta_generic_to_shared(
                    &Asrc[mr + lrow][kc * 64 + ks * 16 + lcol8]);
                ldsm_x4(a0, a1, a2, a3, aAddr);
#pragma unroll
                for (int np = 0; np < 4; np++) {
                    unsigned b0, b1, b2, b3;
                    unsigned bAddr = (unsigned)__cvta_generic_to_shared(
                        &Ws[ks * 16 + lrow][nc + np * 16 + lcol8]);
                    ldsm_x4_t(b0, b1, b2, b3, bAddr);
                    mma16816(acc[np * 2],     a0, a1, a2, a3, b0, b1);
                    mma16816(acc[np * 2 + 1], a0, a1, a2, a3, b2, b3);
                }
            }
        }
    }

    int g0 = rows[r0];
    int g1 = rows[r0 + 8];
#pragma unroll
    for (int nt = 0; nt < 8; nt++) {
        int c = cb + nt * 8;
        float2 bv = *((const float2*)&bias[c]);
        if (g0 >= 0) {
            *((float2*)&out[g0 * DHID + c]) =
                make_float2(fmaxf(acc[nt][0] + bv.x, 0.f), fmaxf(acc[nt][1] + bv.y, 0.f));
        }
        if (g1 >= 0) {
            *((float2*)&out[g1 * DHID + c]) =
                make_float2(fmaxf(acc[nt][2] + bv.x, 0.f), fmaxf(acc[nt][3] + bv.y, 0.f));
        }
    }
}

// ---------------- launch ----------------
extern "C" void kernel_launch(void* const* d_in, const int* in_sizes, int n_in,
                              void* d_out, int out_size) {
    const float* x     = (const float*)d_in[0];
    const int*   ntype = (const int*)d_in[1];
    const int*   src   = (const int*)d_in[2];
    const int*   dst   = (const int*)d_in[3];
    const int*   etype = (const int*)d_in[4];
    const float* wck   = (const float*)d_in[5];
    const float* wbk   = (const float*)d_in[6];
    const float* wcq   = (const float*)d_in[7];
    const float* wbq   = (const float*)d_in[8];
    const float* wcv   = (const float*)d_in[9];
    const float* wbv   = (const float*)d_in[10];
    const float* wca   = (const float*)d_in[11];
    const float* wba   = (const float*)d_in[12];
    const float* pri   = (const float*)d_in[13];
    const float* att   = (const float*)d_in[14];
    const float* msg   = (const float*)d_in[15];
    const float* loopw = (const float*)d_in[16];
    const float* bias  = (const float*)d_in[17];
    float* out = (float*)d_out;

    k_init<<<(N_NODES + 255) / 256, 256>>>();
    k_prepW<<<(4 * TN * DIN * DHID + 255) / 256, 256>>>(wck, wbk, wcq, wbq, wcv, wbv, wca, wba, loopw);
    k_count<<<(N_EDGES + 255) / 256, 256>>>(ntype, dst);
    k_scanA<<<NCHUNK, 1024>>>();
    k_scanB<<<1, 32>>>();
    k_scanC<<<NCHUNK, 1024>>>();
    k_scatter<<<(N_EDGES + 255) / 256, 256>>>(ntype, src, dst, etype);
    k_proj<<<dim3((N_NODES + 63) / 64, TN), 256>>>(x);
    k_qtvt<<<dim3((N_NODES + 63) / 64, NH), 256>>>(att, msg, pri);
    k_logits<<<dim3((N_EDGES + 255) / 256, NH), 256>>>();
    k_agg<<<N_NODES, 256>>>();
    k_out<<<dim3((N_NODES + 63) / 64, TN), 256>>>(x, bias, out);
}